// round 2
// baseline (speedup 1.0000x reference)
#include <cuda_runtime.h>
#include <mma.h>

using namespace nvcuda;

#define B_ 4096
#define H_ 1024
#define E_ 1024
#define V_ 32000

// Scratch (device-global arrays: allocation-free per harness rules)
__device__ float g_zf[(size_t)B_ * H_];
__device__ float g_zi[(size_t)B_ * H_];
__device__ float g_zc[(size_t)B_ * H_];
__device__ float g_zo[(size_t)B_ * H_];
__device__ float g_ct[(size_t)B_ * H_];   // fallback if tuple outputs not in d_out
__device__ float g_ht[(size_t)B_ * H_];

constexpr int BM = 128, BN = 128, BK = 32;
constexpr int APAD = 8, BPAD = 8;

__device__ __forceinline__ float sigmoidf_(float x) {
    return 1.0f / (1.0f + expf(-x));
}

__device__ __forceinline__ float4 to_tf32x4(float4 v) {
    v.x = wmma::__float_to_tf32(v.x);
    v.y = wmma::__float_to_tf32(v.y);
    v.z = wmma::__float_to_tf32(v.z);
    v.w = wmma::__float_to_tf32(v.w);
    return v;
}

// C = epilogue( sum_p A_p @ W_p  [+ C if MODE==1] )
// MODE: 0 = store, 1 = accumulate onto existing C, 2 = sigmoid(store)
// All of M, N, K are exact multiples of the tile sizes by construction.
template <int MODE, int NPAIR>
__global__ __launch_bounds__(256) void gemm_tf32(
    const float* __restrict__ A0, const float* __restrict__ W0,
    const float* __restrict__ A1, const float* __restrict__ W1,
    const float* __restrict__ A2, const float* __restrict__ W2,
    float* __restrict__ C, int M, int N, int K)
{
    __shared__ __align__(16) float As[BM][BK + APAD];   // 128 x 40
    __shared__ __align__(16) float Bs[BK][BN + BPAD];   // 32 x 136

    const int tid    = threadIdx.x;
    const int wid    = tid >> 5;
    const int warp_m = wid & 3;        // 4 warps along M (32 rows each)
    const int warp_n = wid >> 2;       // 2 warps along N (64 cols each)
    const int bm     = blockIdx.y * BM;
    const int bn     = blockIdx.x * BN;

    wmma::fragment<wmma::accumulator, 16, 16, 8, float> acc[2][4];

    #pragma unroll
    for (int i = 0; i < 2; i++) {
        #pragma unroll
        for (int j = 0; j < 4; j++) {
            if (MODE == 1) {
                const float* cp = C + (size_t)(bm + warp_m * 32 + i * 16) * N
                                    + (bn + warp_n * 64 + j * 16);
                wmma::load_matrix_sync(acc[i][j], cp, N, wmma::mem_row_major);
            } else {
                wmma::fill_fragment(acc[i][j], 0.0f);
            }
        }
    }

    const float* Aps[3] = {A0, A1, A2};
    const float* Wps[3] = {W0, W1, W2};

    #pragma unroll 1
    for (int p = 0; p < NPAIR; p++) {
        const float* __restrict__ A = Aps[p];
        const float* __restrict__ W = Wps[p];

        #pragma unroll 1
        for (int k0 = 0; k0 < K; k0 += BK) {
            // --- load A tile [128 x 32], round to tf32 at smem fill ---
            {
                const int r = tid >> 3;            // 0..31
                const int cc = (tid & 7) * 4;      // 0..28
                #pragma unroll
                for (int rr = 0; rr < 4; rr++) {
                    float4 v = *(const float4*)(A + (size_t)(bm + r + rr * 32) * K + k0 + cc);
                    *(float4*)&As[r + rr * 32][cc] = to_tf32x4(v);
                }
            }
            // --- load B tile [32 x 128], round to tf32 at smem fill ---
            {
                const int r = tid >> 5;            // 0..7
                const int cc = (tid & 31) * 4;     // 0..124
                #pragma unroll
                for (int rr = 0; rr < 4; rr++) {
                    float4 v = *(const float4*)(W + (size_t)(k0 + r + rr * 8) * N + bn + cc);
                    *(float4*)&Bs[r + rr * 8][cc] = to_tf32x4(v);
                }
            }
            __syncthreads();

            #pragma unroll
            for (int kk = 0; kk < BK; kk += 8) {
                wmma::fragment<wmma::matrix_a, 16, 16, 8, wmma::precision::tf32, wmma::row_major> af[2];
                wmma::fragment<wmma::matrix_b, 16, 16, 8, wmma::precision::tf32, wmma::row_major> bf[4];

                #pragma unroll
                for (int i = 0; i < 2; i++)
                    wmma::load_matrix_sync(af[i], &As[warp_m * 32 + i * 16][kk], BK + APAD);
                #pragma unroll
                for (int j = 0; j < 4; j++)
                    wmma::load_matrix_sync(bf[j], &Bs[kk][warp_n * 64 + j * 16], BN + BPAD);

                #pragma unroll
                for (int i = 0; i < 2; i++)
                    #pragma unroll
                    for (int j = 0; j < 4; j++)
                        wmma::mma_sync(acc[i][j], af[i], bf[j], acc[i][j]);
            }
            __syncthreads();
        }
    }

    // --- epilogue ---
    #pragma unroll
    for (int i = 0; i < 2; i++) {
        #pragma unroll
        for (int j = 0; j < 4; j++) {
            if (MODE == 2) {
                #pragma unroll
                for (int t = 0; t < acc[i][j].num_elements; t++)
                    acc[i][j].x[t] = sigmoidf_(acc[i][j].x[t]);
            }
            float* cp = C + (size_t)(bm + warp_m * 32 + i * 16) * N
                          + (bn + warp_n * 64 + j * 16);
            wmma::store_matrix_sync(cp, acc[i][j], N, wmma::mem_row_major);
        }
    }
}

// Ct = sigmoid(zf)*c + sigmoid(zi)*tanh(zc)
__global__ void lstm_ew1(const float* __restrict__ zf, const float* __restrict__ zi,
                         const float* __restrict__ zc, const float* __restrict__ c,
                         float* __restrict__ ct, int n)
{
    int i = blockIdx.x * blockDim.x + threadIdx.x;
    if (i < n) {
        float Ft = sigmoidf_(zf[i]);
        float It = sigmoidf_(zi[i]);
        float Cd = tanhf(zc[i]);
        ct[i] = Ft * c[i] + It * Cd;
    }
}

// Ht = sigmoid(zo)*tanh(Ct)
__global__ void lstm_ew2(const float* __restrict__ zo, const float* __restrict__ ct,
                         float* __restrict__ ht, int n)
{
    int i = blockIdx.x * blockDim.x + threadIdx.x;
    if (i < n) {
        float Ot = sigmoidf_(zo[i]);
        ht[i] = Ot * tanhf(ct[i]);
    }
}

extern "C" void kernel_launch(void* const* d_in, const int* in_sizes, int n_in,
                              void* d_out, int out_size)
{
    const float* x          = (const float*)d_in[0];
    const float* h          = (const float*)d_in[1];
    const float* c          = (const float*)d_in[2];
    const float* w_forget   = (const float*)d_in[3];
    const float* w_input    = (const float*)d_in[4];
    const float* w_output   = (const float*)d_in[5];
    const float* w_c_dash   = (const float*)d_in[6];
    const float* w_forget_c = (const float*)d_in[7];
    const float* w_input_c  = (const float*)d_in[8];
    const float* w_output_c = (const float*)d_in[9];
    const float* w_op       = (const float*)d_in[10];
    const float* w_ip_f     = (const float*)d_in[11];
    const float* w_ip_i     = (const float*)d_in[12];
    const float* w_ip_o     = (const float*)d_in[13];
    const float* w_ip_c     = (const float*)d_in[14];
    float* out = (float*)d_out;

    float *zf, *zi, *zc, *zo, *ctbuf, *htbuf;
    cudaGetSymbolAddress((void**)&zf, g_zf);
    cudaGetSymbolAddress((void**)&zi, g_zi);
    cudaGetSymbolAddress((void**)&zc, g_zc);
    cudaGetSymbolAddress((void**)&zo, g_zo);
    cudaGetSymbolAddress((void**)&ctbuf, g_ct);
    cudaGetSymbolAddress((void**)&htbuf, g_ht);

    const size_t BV = (size_t)B_ * V_;
    const size_t BH = (size_t)B_ * H_;

    // Tuple output layout: [Yt | Ht | Ct]. If the harness only keeps Yt,
    // fall back to scratch for Ht/Ct.
    float* ht_out = ((size_t)out_size >= BV + 2 * BH) ? (out + BV)      : htbuf;
    float* ct_out = ((size_t)out_size >= BV + 2 * BH) ? (out + BV + BH) : ctbuf;

    dim3 blk(256);
    dim3 g_h(H_ / BN, B_ / BM);     // (8, 32)
    dim3 g_v(V_ / BN, B_ / BM);     // (250, 32)

    // Gate pre-activations
    gemm_tf32<0, 3><<<g_h, blk>>>(x, w_ip_f, h, w_forget, c, w_forget_c, zf, B_, H_, 1024);
    gemm_tf32<0, 3><<<g_h, blk>>>(x, w_ip_i, h, w_input,  c, w_input_c,  zi, B_, H_, 1024);
    gemm_tf32<0, 2><<<g_h, blk>>>(x, w_ip_c, h, w_c_dash, nullptr, nullptr, zc, B_, H_, 1024);
    gemm_tf32<0, 2><<<g_h, blk>>>(x, w_ip_o, h, w_output, nullptr, nullptr, zo, B_, H_, 1024);

    // Ct
    lstm_ew1<<<(unsigned)(BH / 256), blk>>>(zf, zi, zc, c, ct_out, (int)BH);

    // zo += Ct @ w_output_c
    gemm_tf32<1, 1><<<g_h, blk>>>(ct_out, w_output_c, nullptr, nullptr, nullptr, nullptr,
                                  zo, B_, H_, H_);

    // Ht
    lstm_ew2<<<(unsigned)(BH / 256), blk>>>(zo, ct_out, ht_out, (int)BH);

    // Yt = sigmoid(Ht @ w_op)
    gemm_tf32<2, 1><<<g_v, blk>>>(ht_out, w_op, nullptr, nullptr, nullptr, nullptr,
                                  out, B_, V_, H_);
}